// round 16
// baseline (speedup 1.0000x reference)
#include <cuda_runtime.h>
#include <cstdint>
#include <math.h>

#define BATCH 32
#define TT    2048
#define DD    128
#define FF    16
#define SS    64
#define RR    64
#define STATE 1024
#define TWO_PI_F 6.2831853071795864769f

// scratch (device globals: no allocation)
__device__ float g_traj[(size_t)BATCH * TT * STATE];   // 256 MB state trajectory
__device__ float g_xs[(size_t)BATCH * TT * SS];        // 16 MB  x @ Ws[0:128]

// ---------------- helpers ----------------
__device__ __forceinline__ float gelu1(float v) {
    return 0.5f * v * (1.0f + erff(v * 0.70710678118654752440f));
}
__device__ __forceinline__ unsigned long long pk2(float lo, float hi) {
    unsigned long long u;
    asm("mov.b64 %0, {%1,%2};" : "=l"(u) : "f"(lo), "f"(hi));
    return u;
}
__device__ __forceinline__ void fma2(unsigned long long& d, unsigned long long a,
                                     unsigned long long b) {
    asm("fma.rn.f32x2 %0, %1, %2, %0;" : "+l"(d) : "l"(a), "l"(b));
}
__device__ __forceinline__ float2 up2(unsigned long long u) {
    float2 r;
    asm("mov.b64 {%0,%1}, %2;" : "=f"(r.x), "=f"(r.y) : "l"(u));
    return r;
}

// ==========================================================================
// Kernel 1: xs[b,t,j] = sum_{k<128} x[b,t,k] * Ws[k,j]   (plain CUDA)
// ==========================================================================
__global__ __launch_bounds__(256) void fru_xs(const float* __restrict__ x,
                                              const float* __restrict__ Ws) {
    __shared__ float xsm[32][128];
    __shared__ float wsm[128][64];
    const int tid = threadIdx.x;
    const size_t row0 = (size_t)blockIdx.x * 32;

    for (int i = tid; i < 128 * 64; i += 256) wsm[i >> 6][i & 63] = Ws[i];
    for (int i = tid; i < 32 * 128; i += 256) xsm[i >> 7][i & 127] = x[row0 * 128 + i];
    __syncthreads();

    const int j  = tid & 63;
    const int rq = tid >> 6;
    float acc[8];
#pragma unroll
    for (int i = 0; i < 8; ++i) acc[i] = 0.f;
    for (int k = 0; k < 128; ++k) {
        float w = wsm[k][j];
#pragma unroll
        for (int i = 0; i < 8; ++i) acc[i] = fmaf(xsm[rq * 8 + i][k], w, acc[i]);
    }
#pragma unroll
    for (int i = 0; i < 8; ++i) g_xs[(row0 + rq * 8 + i) * SS + j] = acc[i];
}

// ==========================================================================
// Kernel 2: sequential recurrence. ONE CTA per batch, 1024 threads.
// No clusters, no DSMEM, no inline asm — only __syncthreads().
// Thread (j = tid&63, s = tid>>6): recur GEMV k-slice [s*64, s*64+64):
//   first 32 k's from registers, last 32 k's from 128 KB dynamic smem.
// Thread tid owns state element tid (f = tid>>6, sidx = tid&63).
// ==========================================================================
__global__ __launch_bounds__(1024, 1)
void fru_phaseA(const float* __restrict__ Wr, const float* __restrict__ br,
                const float* __restrict__ Ws, const float* __restrict__ bs,
                const float* __restrict__ phases) {
    extern __shared__ float Wsm[];          // 16*32*64 = 32768 floats (128 KB)
                                            // layout: [s][q][j], q = k - s*64 - 32
    __shared__ __align__(16) float state_sm[STATE];
    __shared__ float Ws2[RR * SS];          // recur-rows of stats matrix (16 KB)
    __shared__ float part_r[16 * 64];
    __shared__ float part_s[16 * 64];
    __shared__ float recur_sm[64];
    __shared__ float stats_sm[64];

    const int tid = threadIdx.x;
    const int b = blockIdx.x;
    const int j = tid & 63;
    const int s = tid >> 6;                 // 0..15 (== frequency f of owned elem)

    // init smem
    for (int e = tid; e < STATE; e += 1024) state_sm[e] = 0.f;
    for (int e = tid; e < RR * SS; e += 1024) Ws2[e] = Ws[(size_t)DD * SS + e];
    // W smem half: Wsm[s][q][j] = Wr[(s*64 + 32 + q)*64 + j]
    for (int e = tid; e < 16 * 32 * 64; e += 1024) {
        int se = e >> 11, qe = (e >> 6) & 31, je = e & 63;
        Wsm[e] = Wr[(size_t)(se * 64 + 32 + qe) * RR + je];
    }
    // W register half: k in [s*64, s*64+32)
    float wreg[32];
#pragma unroll
    for (int q = 0; q < 32; ++q)
        wreg[q] = Wr[(size_t)(s * 64 + q) * RR + j];

    const float my_br = br[j];
    const float my_bs = bs[j];

    // state-update params for owned element tid: f = s
    const float fm   = (s == 0) ? 0.f : 1.f;
    const float a2   = TWO_PI_F * phases[s];
    const float wang = (TWO_PI_F / (float)TT) * (float)s;
    const float invL = 1.f / (float)TT;

    const float* xs_p = g_xs + (size_t)b * TT * SS + tid;      // valid for tid<64
    float* traj_p = g_traj + (size_t)b * TT * STATE + tid;

    const float4* stv = reinterpret_cast<const float4*>(state_sm + s * 64);
    const float*  wsp = Wsm + s * 32 * 64 + j;                 // stride 64
    __syncthreads();

    for (int t = 0; t < TT; ++t) {
        // off the critical path: cos factor + xs prefetch
        const float cosw = invL * cosf(fmaf(wang, (float)(t + 1), a2));
        float xsv = 0.f;
        if (tid < 64) xsv = xs_p[(size_t)t * SS];

        // ---- 1. recur GEMV partial over k-slice ----
        float acc = 0.f;
#pragma unroll
        for (int q4 = 0; q4 < 8; ++q4) {               // reg half (k offsets 0..31)
            float4 sv = stv[q4];
            acc = fmaf(sv.x, wreg[q4 * 4 + 0], acc);
            acc = fmaf(sv.y, wreg[q4 * 4 + 1], acc);
            acc = fmaf(sv.z, wreg[q4 * 4 + 2], acc);
            acc = fmaf(sv.w, wreg[q4 * 4 + 3], acc);
        }
#pragma unroll
        for (int q4 = 0; q4 < 8; ++q4) {               // smem half (k offsets 32..63)
            float4 sv = stv[8 + q4];
            acc = fmaf(sv.x, wsp[(q4 * 4 + 0) * 64], acc);
            acc = fmaf(sv.y, wsp[(q4 * 4 + 1) * 64], acc);
            acc = fmaf(sv.z, wsp[(q4 * 4 + 2) * 64], acc);
            acc = fmaf(sv.w, wsp[(q4 * 4 + 3) * 64], acc);
        }
        part_r[tid] = acc;
        __syncthreads();

        // ---- 2. recur = gelu(sum of 16 partials + br) ----
        if (tid < 64) {
            float red = 0.f;
#pragma unroll
            for (int q = 0; q < 16; ++q) red += part_r[q * 64 + tid];
            recur_sm[tid] = gelu1(red + my_br);
        }
        __syncthreads();

        // ---- 3. stats GEMV partials (k-sliced: 4 recur rows per thread) ----
        {
            float a = 0.f;
#pragma unroll
            for (int r = 0; r < 4; ++r)
                a = fmaf(recur_sm[s * 4 + r], Ws2[(s * 4 + r) * 64 + j], a);
            part_s[tid] = a;
        }
        __syncthreads();

        // ---- 4. stats = gelu(sum + xs + bs) ----
        if (tid < 64) {
            float acc2 = xsv + my_bs;
#pragma unroll
            for (int q = 0; q < 16; ++q) acc2 += part_s[q * 64 + tid];
            stats_sm[tid] = gelu1(acc2);
        }
        __syncthreads();

        // ---- 5. state update + trajectory store ----
        float st = fmaf(cosw, stats_sm[j], fm * state_sm[tid]);
        state_sm[tid] = st;
        traj_p[(size_t)t * STATE] = st;
        __syncthreads();
    }
}

// ==========================================================================
// Kernel 3: out[n,m] = gelu(sum_k traj[n,k]*Wo[k,m] + bo[m])
// N=65536, M=K=1024. 128x128x16 tiles, 256 thr, 8x8 micro.
// f32x2 FMA (arith-only asm); all smem access via plain C++ derefs.
// ==========================================================================
__global__ __launch_bounds__(256, 2)
void fru_gemm(const float* __restrict__ Wo, const float* __restrict__ bo,
              float* __restrict__ out) {
    __shared__ __align__(16) float As[16 * 128];   // [k][i] (A transposed)
    __shared__ __align__(16) float Bs[16 * 128];   // [k][j]

    const int tid = threadIdx.x;
    const size_t n0 = (size_t)blockIdx.y * 128;
    const int m0 = blockIdx.x * 128;

    const int arow = tid >> 1, ac = (tid & 1) * 8;
    const int brow = tid >> 4, bc = (tid & 15) * 8;
    const float* gA = g_traj + (n0 + arow) * (size_t)STATE + ac;
    const float* gB = Wo + (size_t)brow * STATE + m0 + bc;

    float4 a0 = *(const float4*)gA;
    float4 a1 = *(const float4*)(gA + 4);
    float4 b0 = *(const float4*)gB;
    float4 b1 = *(const float4*)(gB + 4);
    {
        float av[8] = {a0.x, a0.y, a0.z, a0.w, a1.x, a1.y, a1.z, a1.w};
#pragma unroll
        for (int c = 0; c < 8; ++c) As[(ac + c) * 128 + arow] = av[c];
        *(float4*)&Bs[brow * 128 + bc] = b0;
        *(float4*)&Bs[brow * 128 + bc + 4] = b1;
    }
    __syncthreads();

    const int i0 = (tid >> 4) * 8, j0 = (tid & 15) * 8;
    unsigned long long acc[8][4];
#pragma unroll
    for (int i = 0; i < 8; ++i)
#pragma unroll
        for (int p = 0; p < 4; ++p) acc[i][p] = 0ull;

    for (int kt = 0; kt < 64; ++kt) {
        if (kt < 63) {
            const float* pA = gA + (size_t)(kt + 1) * 16;
            const float* pB = gB + (size_t)(kt + 1) * 16 * STATE;
            a0 = *(const float4*)pA;       a1 = *(const float4*)(pA + 4);
            b0 = *(const float4*)pB;       b1 = *(const float4*)(pB + 4);
        }
#pragma unroll
        for (int k = 0; k < 16; ++k) {
            float4 av0 = *(const float4*)&As[k * 128 + i0];
            float4 av1 = *(const float4*)&As[k * 128 + i0 + 4];
            ulonglong2 bq0 = *(const ulonglong2*)&Bs[k * 128 + j0];      // j0..j0+3
            ulonglong2 bq1 = *(const ulonglong2*)&Bs[k * 128 + j0 + 4];  // j0+4..j0+7
            float aval[8] = {av0.x, av0.y, av0.z, av0.w, av1.x, av1.y, av1.z, av1.w};
#pragma unroll
            for (int i = 0; i < 8; ++i) {
                unsigned long long aa = pk2(aval[i], aval[i]);
                fma2(acc[i][0], aa, bq0.x);
                fma2(acc[i][1], aa, bq0.y);
                fma2(acc[i][2], aa, bq1.x);
                fma2(acc[i][3], aa, bq1.y);
            }
        }
        __syncthreads();
        if (kt < 63) {
            float av[8] = {a0.x, a0.y, a0.z, a0.w, a1.x, a1.y, a1.z, a1.w};
#pragma unroll
            for (int c = 0; c < 8; ++c) As[(ac + c) * 128 + arow] = av[c];
            *(float4*)&Bs[brow * 128 + bc] = b0;
            *(float4*)&Bs[brow * 128 + bc + 4] = b1;
        }
        __syncthreads();
    }

    // epilogue: bias + exact gelu
    float bias[8];
#pragma unroll
    for (int p = 0; p < 8; ++p) bias[p] = bo[m0 + j0 + p];
#pragma unroll
    for (int i = 0; i < 8; ++i) {
        float v[8];
#pragma unroll
        for (int p = 0; p < 4; ++p) {
            float2 fp = up2(acc[i][p]);
            v[2 * p] = fp.x; v[2 * p + 1] = fp.y;
        }
        float4 o0, o1;
        o0.x = gelu1(v[0] + bias[0]); o0.y = gelu1(v[1] + bias[1]);
        o0.z = gelu1(v[2] + bias[2]); o0.w = gelu1(v[3] + bias[3]);
        o1.x = gelu1(v[4] + bias[4]); o1.y = gelu1(v[5] + bias[5]);
        o1.z = gelu1(v[6] + bias[6]); o1.w = gelu1(v[7] + bias[7]);
        float* op = out + (n0 + i0 + i) * (size_t)STATE + m0 + j0;
        *(float4*)op = o0;
        *(float4*)(op + 4) = o1;
    }
}

// ==========================================================================
// kernel_launch: inputs identified by element count (order-robust).
// The two 64-element biases are interchangeable (both zero in reference).
// ==========================================================================
extern "C" void kernel_launch(void* const* d_in, const int* in_sizes, int n_in,
                              void* d_out, int out_size) {
    const float* x  = nullptr;   // 8388608
    const float* Wr = nullptr;   // 65536
    const float* br = nullptr;   // 64
    const float* Ws = nullptr;   // 12288
    const float* bs = nullptr;   // 64
    const float* Wo = nullptr;   // 1048576
    const float* bo = nullptr;   // 1024
    const float* ph = nullptr;   // 16

    for (int i = 0; i < n_in; ++i) {
        const float* p = (const float*)d_in[i];
        switch (in_sizes[i]) {
            case 8388608: x  = p; break;
            case 65536:   Wr = p; break;
            case 12288:   Ws = p; break;
            case 1048576: Wo = p; break;
            case 1024:    bo = p; break;
            case 16:      ph = p; break;
            case 64:      if (!br) br = p; else bs = p; break;
            default: break;
        }
    }
    if (!x || !Wr || !br || !Ws || !bs || !Wo || !bo || !ph) {
        x  = (const float*)d_in[0];
        Wr = (const float*)d_in[1];
        br = (const float*)d_in[2];
        Ws = (const float*)d_in[3];
        bs = (const float*)d_in[4];
        Wo = (const float*)d_in[5];
        bo = (const float*)d_in[6];
        ph = (const float*)d_in[7];
    }
    float* out = (float*)d_out;

    const int wsm_bytes = 16 * 32 * 64 * (int)sizeof(float);   // 128 KB dynamic
    static int smem_set = 0;
    if (!smem_set) {
        cudaFuncSetAttribute(fru_phaseA,
                             cudaFuncAttributeMaxDynamicSharedMemorySize, wsm_bytes);
        smem_set = 1;
    }

    fru_xs<<<(BATCH * TT) / 32, 256>>>(x, Ws);
    fru_phaseA<<<BATCH, 1024, wsm_bytes>>>(Wr, br, Ws, bs, ph);
    dim3 g(STATE / 128, (BATCH * TT) / 128);
    fru_gemm<<<g, 256>>>(Wo, bo, out);
}